// round 13
// baseline (speedup 1.0000x reference)
#include <cuda_runtime.h>
#include <cuda_bf16.h>

// Persistent device state; last block resets to 0 so every graph replay
// starts from the same state.
__device__ double       g_acc   = 0.0;
__device__ unsigned int g_count = 0u;

// 16 threads per row, 1 float4 per thread per iteration, 8 iterations.
// Block of 256 threads covers 128 rows. Loads are predicated off for chunks
// entirely beyond the row's valid length n[row] (exact: those elements are
// masked to zero anyway). Measured R10/R11: DRAM fetch is ~128B-line
// granular, and this per-16B-chunk predication is the fastest of the three
// schemes tried (beats both batched-MLP and line-level variants).
__global__ __launch_bounds__(256) void mahal_fused_kernel(
    const float4* __restrict__ yt,
    const float4* __restrict__ yp,
    const float*  __restrict__ param,
    const int*    __restrict__ n,
    float*        __restrict__ out,
    int B)
{
    const float pm = __ldg(&param[0]);
    const float p  = 2.0f / (1.0f + __expf(-pm)) - 1.0f;
    const float coef2 = -2.0f * p / (1.0f + p * p);   // 2*coef

    const int lin = threadIdx.x & 15;                 // chunk-in-row, constant
    const int t0  = lin * 4;                          // first column of my chunk

    float acc = 0.0f;
    const int blockBase = blockIdx.x * (256 * 8);     // first float4 chunk of block

#pragma unroll
    for (int j = 0; j < 8; j++) {
        const int cid = blockBase + j * 256 + threadIdx.x;  // global float4 index
        const int row = cid >> 4;
        const int nv  = __ldg(&n[row]);

        float d0 = 0.0f, d1 = 0.0f, d2 = 0.0f, d3 = 0.0f;
        if (t0 < nv) {
            // chunk intersects the valid prefix: load via L2 (no reuse; skip
            // L1 allocation churn).
            const float4 a = __ldcg(&yt[cid]);
            const float4 b = __ldcg(&yp[cid]);
            d0 = a.x - b.x;                               // t0 < nv guaranteed
            d1 = (t0 + 1 < nv) ? (a.y - b.y) : 0.0f;
            d2 = (t0 + 2 < nv) ? (a.z - b.z) : 0.0f;
            d3 = (t0 + 3 < nv) ? (a.w - b.w) : 0.0f;
        }

        float sumsq = d0 * d0;
        sumsq = fmaf(d1, d1, sumsq);
        sumsq = fmaf(d2, d2, sumsq);
        sumsq = fmaf(d3, d3, sumsq);

        float sumadj = d0 * d1;
        sumadj = fmaf(d1, d2, sumadj);
        sumadj = fmaf(d2, d3, sumadj);

        // cross-chunk adjacent product: my d3 * right-neighbor's d0.
        // Executed by ALL lanes (shfl is warp-collective); skipped lanes carry 0.
        const float nd0 = __shfl_down_sync(0xffffffffu, d0, 1);
        if (lin < 15) sumadj = fmaf(d3, nd0, sumadj);

        const float partial = fmaf(coef2, sumadj, sumsq);
        // All 16 lanes of a row share nv: divide partials independently.
        acc += __fdividef(partial, (float)nv);
    }

    // warp reduce
#pragma unroll
    for (int off = 16; off > 0; off >>= 1)
        acc += __shfl_xor_sync(0xffffffffu, acc, off);

    __shared__ float warp_sums[8];
    __shared__ bool  is_last;
    const int warp = threadIdx.x >> 5;
    const int lane = threadIdx.x & 31;
    if (lane == 0) warp_sums[warp] = acc;
    __syncthreads();

    if (warp == 0) {
        float bs = (lane < 8) ? warp_sums[lane] : 0.0f;
#pragma unroll
        for (int off = 4; off > 0; off >>= 1)
            bs += __shfl_xor_sync(0xffffffffu, bs, off);
        if (lane == 0) {
            atomicAdd(&g_acc, (double)bs);
            __threadfence();
            const unsigned int done = atomicAdd(&g_count, 1u);
            is_last = (done == gridDim.x - 1);
        }
    }
    __syncthreads();

    if (is_last && threadIdx.x == 0) {
        const double total = g_acc;
        out[0]  = (float)(total / (double)B);
        g_acc   = 0.0;
        __threadfence();
        g_count = 0u;
    }
}

extern "C" void kernel_launch(void* const* d_in, const int* in_sizes, int n_in,
                              void* d_out, int out_size) {
    const float4* yt    = (const float4*)d_in[0];  // y_true  (B, 64) fp32
    const float4* yp    = (const float4*)d_in[1];  // y_pred  (B, 64) fp32
    const float*  param = (const float*)d_in[2];   // (1,)
    const int*    n     = (const int*)d_in[3];     // (B,)
    float* out = (float*)d_out;

    const int B = in_sizes[3];                     // batch
    const int blocks = B / 128;                    // 256 thr * 8 it / 16 chunks = 128 rows/block

    mahal_fused_kernel<<<blocks, 256>>>(yt, yp, param, n, out, B);
}

// round 14
// speedup vs baseline: 1.0143x; 1.0143x over previous
#include <cuda_runtime.h>
#include <cuda_bf16.h>

// Persistent device state; last block resets to 0 so every graph replay
// starts from the same state.
__device__ double       g_acc   = 0.0;
__device__ unsigned int g_count = 0u;

// Best measured configuration (68.1us):
//  - 16 threads per row, 1 float4 per thread per iteration, 8 iterations;
//    256-thread block covers 128 rows; fully coalesced LDG.128.
//  - Per-16B-chunk load predication on n[row] (skips ~48% of element loads;
//    DRAM traffic sits at its ~128B-line-granular floor, ~410MB).
//  - __ldcs (evict-first) on the y streams: measured +2.3us faster than
//    __ldcg and default paths.
//  - n loads hoisted ahead of the main loop (predicates ready at loop entry).
//  - Fused single kernel: block partials -> double atomic -> last block
//    finalizes and resets state for graph replay.
// Variants measured and rejected: batched-MLP regs=60 (85.8us),
// line-level predication (70.4us), __ldcg (70.4us), 4-lane/row 64B-stride
// layout (90.2us), separate zero/finalize launches (88.1us).
__global__ __launch_bounds__(256) void mahal_fused_kernel(
    const float4* __restrict__ yt,
    const float4* __restrict__ yp,
    const float*  __restrict__ param,
    const int*    __restrict__ n,
    float*        __restrict__ out,
    int B)
{
    const float pm = __ldg(&param[0]);
    const float p  = 2.0f / (1.0f + __expf(-pm)) - 1.0f;
    const float coef2 = -2.0f * p / (1.0f + p * p);   // 2*coef

    const int lin = threadIdx.x & 15;                 // chunk-in-row, constant
    const int t0  = lin * 4;                          // first column of my chunk

    const int blockBase = blockIdx.x * (256 * 8);     // first float4 chunk of block

    // Hoist all n loads: predicates available before any data load.
    int nv[8];
#pragma unroll
    for (int j = 0; j < 8; j++) {
        const int cid = blockBase + j * 256 + threadIdx.x;
        nv[j] = __ldg(&n[cid >> 4]);
    }

    float acc = 0.0f;

#pragma unroll
    for (int j = 0; j < 8; j++) {
        const int cid = blockBase + j * 256 + threadIdx.x;  // global float4 index
        const int v   = nv[j];

        float d0 = 0.0f, d1 = 0.0f, d2 = 0.0f, d3 = 0.0f;
        if (t0 < v) {
            // chunk intersects the valid prefix: streaming load (evict-first)
            const float4 a = __ldcs(&yt[cid]);
            const float4 b = __ldcs(&yp[cid]);
            d0 = a.x - b.x;                               // t0 < v guaranteed
            d1 = (t0 + 1 < v) ? (a.y - b.y) : 0.0f;
            d2 = (t0 + 2 < v) ? (a.z - b.z) : 0.0f;
            d3 = (t0 + 3 < v) ? (a.w - b.w) : 0.0f;
        }

        float sumsq = d0 * d0;
        sumsq = fmaf(d1, d1, sumsq);
        sumsq = fmaf(d2, d2, sumsq);
        sumsq = fmaf(d3, d3, sumsq);

        float sumadj = d0 * d1;
        sumadj = fmaf(d1, d2, sumadj);
        sumadj = fmaf(d2, d3, sumadj);

        // cross-chunk adjacent product: my d3 * right-neighbor's d0.
        // Executed by ALL lanes (shfl is warp-collective); skipped lanes carry 0.
        const float nd0 = __shfl_down_sync(0xffffffffu, d0, 1);
        if (lin < 15) sumadj = fmaf(d3, nd0, sumadj);

        const float partial = fmaf(coef2, sumadj, sumsq);
        // All 16 lanes of a row share v: divide partials independently.
        acc += __fdividef(partial, (float)v);
    }

    // warp reduce
#pragma unroll
    for (int off = 16; off > 0; off >>= 1)
        acc += __shfl_xor_sync(0xffffffffu, acc, off);

    __shared__ float warp_sums[8];
    __shared__ bool  is_last;
    const int warp = threadIdx.x >> 5;
    const int lane = threadIdx.x & 31;
    if (lane == 0) warp_sums[warp] = acc;
    __syncthreads();

    if (warp == 0) {
        float bs = (lane < 8) ? warp_sums[lane] : 0.0f;
#pragma unroll
        for (int off = 4; off > 0; off >>= 1)
            bs += __shfl_xor_sync(0xffffffffu, bs, off);
        if (lane == 0) {
            atomicAdd(&g_acc, (double)bs);
            __threadfence();
            const unsigned int done = atomicAdd(&g_count, 1u);
            is_last = (done == gridDim.x - 1);
        }
    }
    __syncthreads();

    if (is_last && threadIdx.x == 0) {
        const double total = g_acc;
        out[0]  = (float)(total / (double)B);
        g_acc   = 0.0;
        __threadfence();
        g_count = 0u;
    }
}

extern "C" void kernel_launch(void* const* d_in, const int* in_sizes, int n_in,
                              void* d_out, int out_size) {
    const float4* yt    = (const float4*)d_in[0];  // y_true  (B, 64) fp32
    const float4* yp    = (const float4*)d_in[1];  // y_pred  (B, 64) fp32
    const float*  param = (const float*)d_in[2];   // (1,)
    const int*    n     = (const int*)d_in[3];     // (B,)
    float* out = (float*)d_out;

    const int B = in_sizes[3];                     // batch
    const int blocks = B / 128;                    // 128 rows per block

    mahal_fused_kernel<<<blocks, 256>>>(yt, yp, param, n, out, B);
}

// round 15
// speedup vs baseline: 1.0623x; 1.0473x over previous
#include <cuda_runtime.h>
#include <cuda_bf16.h>

// Persistent device state; last block resets to 0 so every graph replay
// starts from the same state.
__device__ double       g_acc   = 0.0;
__device__ unsigned int g_count = 0u;

// Single-wave persistent grid: 1184 blocks (148 SMs x occ 8) grid-stride over
// tiles of 128 rows each. Inner body is the measured-optimal R6 structure:
//  - 16 threads per row, 1 float4 per thread per j, 8 j's per tile;
//    fully coalesced LDG.128.
//  - Per-16B-chunk load predication on n[row] (exact; ~48% of loads skipped).
//  - __ldcs (evict-first) on the y streams (beat __ldcg/default by 2.3us).
//  - Block partials -> one double atomic per block (1184 total) -> last
//    block finalizes and resets state for graph replay.
__global__ __launch_bounds__(256) void mahal_fused_kernel(
    const float4* __restrict__ yt,
    const float4* __restrict__ yp,
    const float*  __restrict__ param,
    const int*    __restrict__ n,
    float*        __restrict__ out,
    int B,
    int numTiles)
{
    const float pm = __ldg(&param[0]);
    const float p  = 2.0f / (1.0f + __expf(-pm)) - 1.0f;
    const float coef2 = -2.0f * p / (1.0f + p * p);   // 2*coef

    const int lin = threadIdx.x & 15;                 // chunk-in-row, constant
    const int t0  = lin * 4;                          // first column of my chunk

    float acc = 0.0f;

    for (int tile = blockIdx.x; tile < numTiles; tile += gridDim.x) {
        const int tileBase = tile * (256 * 8);        // first float4 chunk of tile

        // Hoist the tile's n loads: predicates ready before data loads.
        int nv[8];
#pragma unroll
        for (int j = 0; j < 8; j++) {
            const int cid = tileBase + j * 256 + threadIdx.x;
            nv[j] = __ldg(&n[cid >> 4]);
        }

#pragma unroll
        for (int j = 0; j < 8; j++) {
            const int cid = tileBase + j * 256 + threadIdx.x;
            const int v   = nv[j];

            float d0 = 0.0f, d1 = 0.0f, d2 = 0.0f, d3 = 0.0f;
            if (t0 < v) {
                const float4 a = __ldcs(&yt[cid]);
                const float4 b = __ldcs(&yp[cid]);
                d0 = a.x - b.x;                       // t0 < v guaranteed
                d1 = (t0 + 1 < v) ? (a.y - b.y) : 0.0f;
                d2 = (t0 + 2 < v) ? (a.z - b.z) : 0.0f;
                d3 = (t0 + 3 < v) ? (a.w - b.w) : 0.0f;
            }

            float sumsq = d0 * d0;
            sumsq = fmaf(d1, d1, sumsq);
            sumsq = fmaf(d2, d2, sumsq);
            sumsq = fmaf(d3, d3, sumsq);

            float sumadj = d0 * d1;
            sumadj = fmaf(d1, d2, sumadj);
            sumadj = fmaf(d2, d3, sumadj);

            // cross-chunk adjacent product: my d3 * right-neighbor's d0.
            // All lanes execute the shfl; lanes with lin==15 skip the fma.
            const float nd0 = __shfl_down_sync(0xffffffffu, d0, 1);
            if (lin < 15) sumadj = fmaf(d3, nd0, sumadj);

            const float partial = fmaf(coef2, sumadj, sumsq);
            // All 16 lanes of a row share v: divide partials independently.
            acc += __fdividef(partial, (float)v);
        }
    }

    // warp reduce
#pragma unroll
    for (int off = 16; off > 0; off >>= 1)
        acc += __shfl_xor_sync(0xffffffffu, acc, off);

    __shared__ float warp_sums[8];
    __shared__ bool  is_last;
    const int warp = threadIdx.x >> 5;
    const int lane = threadIdx.x & 31;
    if (lane == 0) warp_sums[warp] = acc;
    __syncthreads();

    if (warp == 0) {
        float bs = (lane < 8) ? warp_sums[lane] : 0.0f;
#pragma unroll
        for (int off = 4; off > 0; off >>= 1)
            bs += __shfl_xor_sync(0xffffffffu, bs, off);
        if (lane == 0) {
            atomicAdd(&g_acc, (double)bs);
            __threadfence();
            const unsigned int done = atomicAdd(&g_count, 1u);
            is_last = (done == gridDim.x - 1);
        }
    }
    __syncthreads();

    if (is_last && threadIdx.x == 0) {
        const double total = g_acc;
        out[0]  = (float)(total / (double)B);
        g_acc   = 0.0;
        __threadfence();
        g_count = 0u;
    }
}

extern "C" void kernel_launch(void* const* d_in, const int* in_sizes, int n_in,
                              void* d_out, int out_size) {
    const float4* yt    = (const float4*)d_in[0];  // y_true  (B, 64) fp32
    const float4* yp    = (const float4*)d_in[1];  // y_pred  (B, 64) fp32
    const float*  param = (const float*)d_in[2];   // (1,)
    const int*    n     = (const int*)d_in[3];     // (B,)
    float* out = (float*)d_out;

    const int B        = in_sizes[3];              // batch
    const int numTiles = B / 128;                  // 128 rows per tile -> 8192
    const int blocks   = 148 * 8;                  // single wave: 1184 CTAs

    mahal_fused_kernel<<<blocks, 256>>>(yt, yp, param, n, out, B, numTiles);
}